// round 2
// baseline (speedup 1.0000x reference)
#include <cuda_runtime.h>
#include <math.h>

// Problem constants
#define IN_DIM  128
#define OUT_DIM 256
#define NUM_F   8
#define BATCH   1024
#define KF      9                  // 8 sin features + 1 silu feature per input dim
#define KDIM    (IN_DIM * KF)      // 1152

// Scratch (device globals — no allocation allowed)
__device__ float g_W[OUT_DIM * KDIM];   // packed weights [256][1152]
__device__ float g_A[BATCH * KDIM];     // features       [1024][1152]

// ---------------------------------------------------------------------------
// Pack weights: W[o][i*9+f] = scale_sp[n]*coef[n][f] (f<8), W[o][i*9+8] = scale_base[n]
// ---------------------------------------------------------------------------
__global__ void prep_w_kernel(const float* __restrict__ coef,
                              const float* __restrict__ scale_sp,
                              const float* __restrict__ scale_base) {
    int idx = blockIdx.x * blockDim.x + threadIdx.x;
    if (idx >= OUT_DIM * KDIM) return;
    int o = idx / KDIM;
    int k = idx % KDIM;
    int i = k / KF;
    int f = k % KF;
    int n = o * IN_DIM + i;
    float v;
    if (f < NUM_F) v = scale_sp[n] * coef[n * NUM_F + f];
    else           v = scale_base[n];
    g_W[idx] = v;
}

// ---------------------------------------------------------------------------
// Build features: A[b][i*9+f] = sin(grid[f]*x[b,i]);  A[b][i*9+8] = silu(x[b,i])
// ---------------------------------------------------------------------------
__global__ void prep_a_kernel(const float* __restrict__ x,
                              const float* __restrict__ grid) {
    int idx = blockIdx.x * blockDim.x + threadIdx.x;   // b*IN_DIM + i
    if (idx >= BATCH * IN_DIM) return;
    float xv = x[idx];
    int b = idx / IN_DIM;
    int i = idx % IN_DIM;
    float* dst = &g_A[b * KDIM + i * KF];
    #pragma unroll
    for (int f = 0; f < NUM_F; f++) {
        dst[f] = sinf(grid[f] * xv);
    }
    float sig = 1.0f / (1.0f + expf(-xv));
    dst[NUM_F] = xv * sig;
}

// ---------------------------------------------------------------------------
// out[b][o] = bias_w[o]   (GEMM accumulates on top with atomics)
// ---------------------------------------------------------------------------
__global__ void bias_init_kernel(const float* __restrict__ bias_w,
                                 float* __restrict__ out) {
    int idx = blockIdx.x * blockDim.x + threadIdx.x;
    if (idx < BATCH * OUT_DIM) out[idx] = bias_w[idx & (OUT_DIM - 1)];
}

// ---------------------------------------------------------------------------
// fp32 GEMM, register-blocked, packed f32x2 FMA, split-K with fp32 atomics.
// C[1024,256] += A[1024,1152] * W[256,1152]^T
// ---------------------------------------------------------------------------
#define BM 64
#define BN 64
#define BK 8
#define KSPLIT 4
#define KCHUNK (KDIM / KSPLIT)     // 288 (divisible by BK)
#define SPAD 68                    // 64 + 4 pad: bank stride 4 -> conflict-free STS

__global__ __launch_bounds__(256, 2) void gemm_kernel(float* __restrict__ out) {
    __shared__ float As[BK][SPAD];
    __shared__ float Ws[BK][SPAD];

    const int tid = threadIdx.x;
    const int m0 = blockIdx.x * BM;
    const int n0 = blockIdx.y * BN;
    const int k0 = blockIdx.z * KCHUNK;

    const int tx = tid & 15;   // n-subtile: cols tx*4 .. tx*4+3
    const int ty = tid >> 4;   // m-subtile: rows ty*4 .. ty*4+3

    // f32x2 accumulators: acc[m][p] holds cols (tx*4+2p, tx*4+2p+1) for row ty*4+m
    unsigned long long acc[4][2];
    #pragma unroll
    for (int m = 0; m < 4; m++) {
        acc[m][0] = 0ull;
        acc[m][1] = 0ull;
    }

    for (int kk = 0; kk < KCHUNK; kk += BK) {
        // Cooperative tile load: 512 elems each for A and W (2 per thread each)
        #pragma unroll
        for (int t = 0; t < 2; t++) {
            int idx = tid + t * 256;          // 0..511
            int m = idx >> 3;                 // 0..63
            int k = idx & 7;                  // 0..7
            As[k][m] = g_A[(m0 + m) * KDIM + k0 + kk + k];
            Ws[k][m] = g_W[(n0 + m) * KDIM + k0 + kk + k];
        }
        __syncthreads();

        #pragma unroll
        for (int k = 0; k < BK; k++) {
            float4 av = *reinterpret_cast<const float4*>(&As[k][ty * 4]);
            float4 wv = *reinterpret_cast<const float4*>(&Ws[k][tx * 4]);
            unsigned long long w01, w23;
            asm("mov.b64 %0, {%1, %2};" : "=l"(w01) : "f"(wv.x), "f"(wv.y));
            asm("mov.b64 %0, {%1, %2};" : "=l"(w23) : "f"(wv.z), "f"(wv.w));
            float am[4] = {av.x, av.y, av.z, av.w};
            #pragma unroll
            for (int m = 0; m < 4; m++) {
                unsigned long long ad;
                asm("mov.b64 %0, {%1, %1};" : "=l"(ad) : "f"(am[m]));
                asm("fma.rn.f32x2 %0, %1, %2, %0;" : "+l"(acc[m][0]) : "l"(ad), "l"(w01));
                asm("fma.rn.f32x2 %0, %1, %2, %0;" : "+l"(acc[m][1]) : "l"(ad), "l"(w23));
            }
        }
        __syncthreads();
    }

    // Accumulate into output (bias already there); split-K partials via atomics
    #pragma unroll
    for (int m = 0; m < 4; m++) {
        int row = m0 + ty * 4 + m;
        #pragma unroll
        for (int p = 0; p < 2; p++) {
            float lo, hi;
            asm("mov.b64 {%0, %1}, %2;" : "=f"(lo), "=f"(hi) : "l"(acc[m][p]));
            int col = n0 + tx * 4 + 2 * p;
            atomicAdd(&out[row * OUT_DIM + col],     lo);
            atomicAdd(&out[row * OUT_DIM + col + 1], hi);
        }
    }
}

// ---------------------------------------------------------------------------
// kernel_launch
// inputs (metadata order): x[1024*128], grid[8], coef[32768*8],
//                          scale_sp[32768], scale_base[32768], bias_w[256]
// output: float[1024*256]
// ---------------------------------------------------------------------------
extern "C" void kernel_launch(void* const* d_in, const int* in_sizes, int n_in,
                              void* d_out, int out_size) {
    const float* x          = (const float*)d_in[0];
    const float* grid       = (const float*)d_in[1];
    const float* coef       = (const float*)d_in[2];
    const float* scale_sp   = (const float*)d_in[3];
    const float* scale_base = (const float*)d_in[4];
    const float* bias_w     = (const float*)d_in[5];
    float* out = (float*)d_out;

    // 1) pack weights: 256*1152 = 294912 elements
    prep_w_kernel<<<(OUT_DIM * KDIM + 255) / 256, 256>>>(coef, scale_sp, scale_base);

    // 2) features: 1024*128 = 131072 threads
    prep_a_kernel<<<(BATCH * IN_DIM + 255) / 256, 256>>>(x, grid);

    // 3) out = bias
    bias_init_kernel<<<(BATCH * OUT_DIM + 255) / 256, 256>>>(bias_w, out);

    // 4) GEMM with split-K atomic accumulation
    dim3 grid_dim(BATCH / BM, OUT_DIM / BN, KSPLIT);   // (16, 4, 4) = 256 CTAs
    gemm_kernel<<<grid_dim, 256>>>(out);
}

// round 3
// speedup vs baseline: 1.3459x; 1.3459x over previous
#include <cuda_runtime.h>
#include <math.h>

// Problem constants
#define IN_DIM  128
#define OUT_DIM 256
#define NUM_F   8
#define BATCH   1024
#define KF      9                  // 8 sin features + 1 silu feature
#define KDIM    (IN_DIM * KF)      // 1152

// GEMM tiling
#define BM 64
#define BN 128
#define BK 8
#define KSPLIT 16
#define KCHUNK (KDIM / KSPLIT)     // 72

// Scratch (device globals — no allocation allowed)
__device__ __align__(16) float g_Wt[KDIM * OUT_DIM];          // W^T: [1152][256]
__device__ __align__(16) float g_At[KDIM * BATCH];            // A^T: [1152][1024]
__device__ __align__(16) float g_part[KSPLIT * BATCH * OUT_DIM]; // 16MB split-K partials

// ---------------------------------------------------------------------------
// Pack weights (transposed): Wt[k][o], k = i*9+f
//   f<8:  scale_sp[n]*coef[n][f],  f==8: scale_base[n],  n = o*128+i
// ---------------------------------------------------------------------------
__global__ void prep_w_kernel(const float* __restrict__ coef,
                              const float* __restrict__ scale_sp,
                              const float* __restrict__ scale_base) {
    int idx = blockIdx.x * blockDim.x + threadIdx.x;
    if (idx >= KDIM * OUT_DIM) return;
    int o = idx & (OUT_DIM - 1);
    int k = idx >> 8;
    int i = k / KF;
    int f = k - i * KF;
    int n = o * IN_DIM + i;
    float v;
    if (f < NUM_F) v = scale_sp[n] * coef[n * NUM_F + f];
    else           v = scale_base[n];
    g_Wt[idx] = v;
}

// ---------------------------------------------------------------------------
// Build features (transposed): At[i*9+f][b] = sin(grid[f]*x[b,i]);  [..8][b]=silu
// Thread map: consecutive threads -> consecutive b (coalesced stores).
// ---------------------------------------------------------------------------
__global__ void prep_a_kernel(const float* __restrict__ x,
                              const float* __restrict__ grid) {
    int idx = blockIdx.x * blockDim.x + threadIdx.x;   // i*BATCH + b
    if (idx >= BATCH * IN_DIM) return;
    int b = idx & (BATCH - 1);
    int i = idx >> 10;
    float xv = x[b * IN_DIM + i];
    float* dst = &g_At[(i * KF) * BATCH + b];
    #pragma unroll
    for (int f = 0; f < NUM_F; f++) {
        dst[f * BATCH] = __sinf(grid[f] * xv);
    }
    float sig = 1.0f / (1.0f + __expf(-xv));
    dst[NUM_F * BATCH] = xv * sig;
}

// ---------------------------------------------------------------------------
// fp32 GEMM, packed f32x2 FMA, split-K to scratch partials.
// part[s] = A[64-tile, kchunk] * W^T  for each (m-tile, n-tile, s)
// Thread tile 4M x 8N. A stored duplicated in smem so LDS.128 feeds FMA2
// operands with zero MOVs.
// ---------------------------------------------------------------------------
#define FMA2(acc, a, w) asm("fma.rn.f32x2 %0, %1, %2, %0;" : "+l"(acc) : "l"(a), "l"(w))

union U4 { float4 v; unsigned long long u[2]; };

__global__ __launch_bounds__(256, 3) void gemm_kernel() {
    __shared__ __align__(16) float2 As2[BK][BM];   // duplicated A: (a,a)
    __shared__ __align__(16) float  Ws[BK][BN];

    const int tid = threadIdx.x;
    const int m0 = blockIdx.x * BM;
    const int n0 = blockIdx.y * BN;
    const int k0 = blockIdx.z * KCHUNK;

    const int tx8 = (tid & 15) * 8;   // n cols tx8 .. tx8+7
    const int ty4 = (tid >> 4) * 4;   // m rows ty4 .. ty4+3

    unsigned long long acc[4][4];
    #pragma unroll
    for (int m = 0; m < 4; m++)
        #pragma unroll
        for (int j = 0; j < 4; j++) acc[m][j] = 0ull;

    // loader coords
    const int la_m = tid & 63;        // A: m index
    const int la_k = tid >> 6;        // A: k base (0..3), +4 for second
    const int lw_n = tid & 127;       // W: n index
    const int lw_k = tid >> 7;        // W: k base (0..1), +2,+4,+6

    for (int kk = 0; kk < KCHUNK; kk += BK) {
        #pragma unroll
        for (int t = 0; t < 2; t++) {
            int k = la_k + t * 4;
            float v = g_At[(k0 + kk + k) * BATCH + m0 + la_m];
            As2[k][la_m] = make_float2(v, v);
        }
        #pragma unroll
        for (int t = 0; t < 4; t++) {
            int k = lw_k + t * 2;
            Ws[k][lw_n] = g_Wt[(k0 + kk + k) * OUT_DIM + n0 + lw_n];
        }
        __syncthreads();

        #pragma unroll
        for (int k = 0; k < BK; k++) {
            U4 a0, a1, w0, w1;
            a0.v = *reinterpret_cast<const float4*>(&As2[k][ty4]);     // (a0,a0,a1,a1)
            a1.v = *reinterpret_cast<const float4*>(&As2[k][ty4 + 2]); // (a2,a2,a3,a3)
            w0.v = *reinterpret_cast<const float4*>(&Ws[k][tx8]);      // w0..w3
            w1.v = *reinterpret_cast<const float4*>(&Ws[k][tx8 + 4]);  // w4..w7

            FMA2(acc[0][0], a0.u[0], w0.u[0]);
            FMA2(acc[0][1], a0.u[0], w0.u[1]);
            FMA2(acc[0][2], a0.u[0], w1.u[0]);
            FMA2(acc[0][3], a0.u[0], w1.u[1]);
            FMA2(acc[1][0], a0.u[1], w0.u[0]);
            FMA2(acc[1][1], a0.u[1], w0.u[1]);
            FMA2(acc[1][2], a0.u[1], w1.u[0]);
            FMA2(acc[1][3], a0.u[1], w1.u[1]);
            FMA2(acc[2][0], a1.u[0], w0.u[0]);
            FMA2(acc[2][1], a1.u[0], w0.u[1]);
            FMA2(acc[2][2], a1.u[0], w1.u[0]);
            FMA2(acc[2][3], a1.u[0], w1.u[1]);
            FMA2(acc[3][0], a1.u[1], w0.u[0]);
            FMA2(acc[3][1], a1.u[1], w0.u[1]);
            FMA2(acc[3][2], a1.u[1], w1.u[0]);
            FMA2(acc[3][3], a1.u[1], w1.u[1]);
        }
        __syncthreads();
    }

    // Write partials (no atomics): part[s][m0+row][n0+col]
    float* base = &g_part[((size_t)blockIdx.z * BATCH + m0 + ty4) * OUT_DIM + n0 + tx8];
    #pragma unroll
    for (int m = 0; m < 4; m++) {
        U4 o0, o1;
        o0.u[0] = acc[m][0]; o0.u[1] = acc[m][1];
        o1.u[0] = acc[m][2]; o1.u[1] = acc[m][3];
        float* row = base + m * OUT_DIM;
        *reinterpret_cast<float4*>(row)     = o0.v;
        *reinterpret_cast<float4*>(row + 4) = o1.v;
    }
}

// ---------------------------------------------------------------------------
// out[b][o] = bias[o] + sum_s part[s][b][o]    (vectorized float4)
// ---------------------------------------------------------------------------
__global__ void reduce_kernel(const float* __restrict__ bias_w,
                              float* __restrict__ out) {
    int idx = blockIdx.x * blockDim.x + threadIdx.x;   // 0..65535 (float4 units)
    if (idx >= BATCH * OUT_DIM / 4) return;
    int b  = idx >> 6;
    int o4 = idx & 63;
    float4 s = reinterpret_cast<const float4*>(bias_w)[o4];
    const float4* p = reinterpret_cast<const float4*>(g_part);
    #pragma unroll
    for (int k = 0; k < KSPLIT; k++) {
        float4 v = p[((size_t)k * BATCH + b) * (OUT_DIM / 4) + o4];
        s.x += v.x; s.y += v.y; s.z += v.z; s.w += v.w;
    }
    reinterpret_cast<float4*>(out)[idx] = s;
}

// ---------------------------------------------------------------------------
// kernel_launch
// inputs: x[1024*128], grid[8], coef[32768*8], scale_sp[32768],
//         scale_base[32768], bias_w[256];  output: float[1024*256]
// ---------------------------------------------------------------------------
extern "C" void kernel_launch(void* const* d_in, const int* in_sizes, int n_in,
                              void* d_out, int out_size) {
    const float* x          = (const float*)d_in[0];
    const float* grid       = (const float*)d_in[1];
    const float* coef       = (const float*)d_in[2];
    const float* scale_sp   = (const float*)d_in[3];
    const float* scale_base = (const float*)d_in[4];
    const float* bias_w     = (const float*)d_in[5];
    float* out = (float*)d_out;

    prep_w_kernel<<<(KDIM * OUT_DIM + 255) / 256, 256>>>(coef, scale_sp, scale_base);
    prep_a_kernel<<<(BATCH * IN_DIM + 255) / 256, 256>>>(x, grid);

    dim3 grid_dim(BATCH / BM, OUT_DIM / BN, KSPLIT);   // (16, 2, 16) = 512 CTAs
    gemm_kernel<<<grid_dim, 256>>>();

    reduce_kernel<<<(BATCH * OUT_DIM / 4 + 255) / 256, 256>>>(bias_w, out);
}

// round 5
// speedup vs baseline: 1.9084x; 1.4179x over previous
#include <cuda_runtime.h>
#include <cuda_bf16.h>
#include <math.h>
#include <stdint.h>

// ---------------------------------------------------------------- constants
#define IN_DIM  128
#define OUT_DIM 256
#define NUM_F   8
#define BATCH   1024
#define KF      9
#define KDIM    1152                 // 128*9

#define TILE_M  64
#define TILE_N  64
#define BK      64                   // bf16 elems per k-chunk = 128B rows
#define ZSPLIT  2
#define KCH_PER_Z   9                // 576 elems per z per split
#define NSTAGE  27                   // 3 splits * 9 chunks

// ---------------------------------------------------------------- scratch
__device__ __align__(16) __nv_bfloat16 g_Ah[BATCH * KDIM];
__device__ __align__(16) __nv_bfloat16 g_Al[BATCH * KDIM];
__device__ __align__(16) __nv_bfloat16 g_Wh[OUT_DIM * KDIM];
__device__ __align__(16) __nv_bfloat16 g_Wl[OUT_DIM * KDIM];
__device__ __align__(16) float g_p2[ZSPLIT * BATCH * OUT_DIM];   // 2MB partials

// ---------------------------------------------------------------- helpers
__device__ __forceinline__ uint32_t smem_u32(const void* p) {
    uint32_t a;
    asm("{ .reg .u64 t; cvta.to.shared.u64 t, %1; cvt.u32.u64 %0, t; }" : "=r"(a) : "l"(p));
    return a;
}
#define CP_ASYNC16(dst, src) \
    asm volatile("cp.async.cg.shared.global [%0], [%1], 16;" :: "r"(dst), "l"(src))
#define CP_COMMIT() asm volatile("cp.async.commit_group;" ::: "memory")
#define CP_WAIT(n)  asm volatile("cp.async.wait_group %0;" :: "n"(n) : "memory")

#define LDSM_X4(r0, r1, r2, r3, addr)                                         \
    asm volatile("ldmatrix.sync.aligned.m8n8.x4.shared.b16 {%0,%1,%2,%3}, [%4];" \
                 : "=r"(r0), "=r"(r1), "=r"(r2), "=r"(r3) : "r"(addr))
#define LDSM_X2(r0, r1, addr)                                                 \
    asm volatile("ldmatrix.sync.aligned.m8n8.x2.shared.b16 {%0,%1}, [%2];"    \
                 : "=r"(r0), "=r"(r1) : "r"(addr))

#define MMA16816(c, a, b)                                                     \
    asm volatile("mma.sync.aligned.m16n8k16.row.col.f32.bf16.bf16.f32 "       \
                 "{%0,%1,%2,%3}, {%4,%5,%6,%7}, {%8,%9}, {%0,%1,%2,%3};"      \
                 : "+f"((c)[0]), "+f"((c)[1]), "+f"((c)[2]), "+f"((c)[3])     \
                 : "r"((a)[0]), "r"((a)[1]), "r"((a)[2]), "r"((a)[3]),        \
                   "r"((b)[0]), "r"((b)[1]))

// ---------------------------------------------------------------- prep W
// one thread per n = o*128+i: reads coef[n][0..7] (32B), writes 9 hi + 9 lo bf16
__global__ void prep_w_kernel(const float* __restrict__ coef,
                              const float* __restrict__ scale_sp,
                              const float* __restrict__ scale_base) {
    int n = blockIdx.x * blockDim.x + threadIdx.x;   // o*128 + i
    if (n >= OUT_DIM * IN_DIM) return;
    int o = n >> 7;
    int i = n & 127;
    float sp = scale_sp[n];
    float sb = scale_base[n];
    __nv_bfloat16* dh = &g_Wh[(size_t)o * KDIM + i * KF];
    __nv_bfloat16* dl = &g_Wl[(size_t)o * KDIM + i * KF];
    float4 c0 = reinterpret_cast<const float4*>(coef + (size_t)n * NUM_F)[0];
    float4 c1 = reinterpret_cast<const float4*>(coef + (size_t)n * NUM_F)[1];
    float v[KF] = {c0.x, c0.y, c0.z, c0.w, c1.x, c1.y, c1.z, c1.w, 0.0f};
    #pragma unroll
    for (int f = 0; f < NUM_F; f++) v[f] *= sp;
    v[NUM_F] = sb;
    #pragma unroll
    for (int f = 0; f < KF; f++) {
        __nv_bfloat16 hi = __float2bfloat16(v[f]);
        dh[f] = hi;
        dl[f] = __float2bfloat16(v[f] - __bfloat162float(hi));
    }
}

// ---------------------------------------------------------------- prep A
__global__ void prep_a_kernel(const float* __restrict__ x,
                              const float* __restrict__ grid) {
    int idx = blockIdx.x * blockDim.x + threadIdx.x;   // b*128 + i
    if (idx >= BATCH * IN_DIM) return;
    float xv = x[idx];
    int b = idx >> 7;
    int i = idx & 127;
    __nv_bfloat16* dh = &g_Ah[(size_t)b * KDIM + i * KF];
    __nv_bfloat16* dl = &g_Al[(size_t)b * KDIM + i * KF];
    float vals[KF];
    #pragma unroll
    for (int f = 0; f < NUM_F; f++) vals[f] = __sinf(grid[f] * xv);
    vals[NUM_F] = xv / (1.0f + __expf(-xv));
    #pragma unroll
    for (int f = 0; f < KF; f++) {
        __nv_bfloat16 hi = __float2bfloat16(vals[f]);
        dh[f] = hi;
        dl[f] = __float2bfloat16(vals[f] - __bfloat162float(hi));
    }
}

// ---------------------------------------------------------------- GEMM
// grid (16, 4, 2).  For z-half of K, accumulate Ah*Wh + Al*Wh + Ah*Wl into
// fp32 accumulators; write p2[z].  mma.m16n8k16 bf16, ldmatrix, cp.async x2.
// smem: A buf0 @0, A buf1 @8192, W buf0 @16384, W buf1 @24576  (SW128 swizzle)
__global__ __launch_bounds__(256, 1) void gemm_kernel() {
    __shared__ __align__(128) uint8_t smem[4 * 8192];

    const int tid = threadIdx.x;
    const int wid = tid >> 5;
    const int lid = tid & 31;
    const int wm  = wid >> 2;          // 0..1  -> m rows wm*32
    const int wn  = wid & 3;           // 0..3  -> n cols wn*16
    const int m0  = blockIdx.x * TILE_M;
    const int n0  = blockIdx.y * TILE_N;
    const int z   = blockIdx.z;

    const uint32_t smbase = smem_u32(smem);

    // loader per-thread coords (2 iters each for A and W: 512 x 16B per tile)
    const int lrow0 = tid >> 3;            // 0..31
    const int lc16  = tid & 7;             // 16B unit in row
    const uint32_t lsw0 = (uint32_t)((lc16 * 16) ^ ((lrow0 & 7) * 16));
    const uint32_t ldst0 = (uint32_t)(lrow0 * 128) + lsw0;       // rows 0..31
    const uint32_t ldst1 = (uint32_t)((lrow0 + 32) * 128) + lsw0; // rows 32..63
    const size_t lsrcA0 = (size_t)(m0 + lrow0) * KDIM + lc16 * 8;
    const size_t lsrcA1 = (size_t)(m0 + lrow0 + 32) * KDIM + lc16 * 8;
    const size_t lsrcW0 = (size_t)(n0 + lrow0) * KDIM + lc16 * 8;
    const size_t lsrcW1 = (size_t)(n0 + lrow0 + 32) * KDIM + lc16 * 8;

    // ldmatrix per-thread coords
    const uint32_t swz  = (uint32_t)((lid & 7) * 16);
    const uint32_t acol = (uint32_t)((lid >> 4) * 16);
    const uint32_t bcol = (uint32_t)(((lid >> 3) & 1) * 16);
    const uint32_t arow0 = (uint32_t)((wm * 32 + (lid & 15)) * 128);
    const uint32_t arow1 = arow0 + 16 * 128;
    const uint32_t brow0 = (uint32_t)((wn * 16 + (lid & 7)) * 128);
    const uint32_t brow1 = brow0 + 8 * 128;

    float acc[2][2][4];
    #pragma unroll
    for (int mi = 0; mi < 2; mi++)
        #pragma unroll
        for (int ni = 0; ni < 2; ni++)
            #pragma unroll
            for (int r = 0; r < 4; r++) acc[mi][ni][r] = 0.0f;

    // stage s: split sp = s/9, chunk j = s%9, k offset = (z*9 + j)*64
    auto issue_stage = [&](int s, int buf) {
        int sp = s / KCH_PER_Z;
        int j  = s - sp * KCH_PER_Z;
        const __nv_bfloat16* A = (sp == 1) ? g_Al : g_Ah;
        const __nv_bfloat16* W = (sp == 2) ? g_Wl : g_Wh;
        int kofs = (z * KCH_PER_Z + j) * BK;
        uint32_t dA = smbase + buf * 8192;
        uint32_t dW = smbase + 16384 + buf * 8192;
        CP_ASYNC16(dA + ldst0, A + lsrcA0 + kofs);
        CP_ASYNC16(dA + ldst1, A + lsrcA1 + kofs);
        CP_ASYNC16(dW + ldst0, W + lsrcW0 + kofs);
        CP_ASYNC16(dW + ldst1, W + lsrcW1 + kofs);
    };

    issue_stage(0, 0); CP_COMMIT();
    issue_stage(1, 1); CP_COMMIT();

    for (int s = 0; s < NSTAGE; s++) {
        if (s + 2 < NSTAGE) { CP_WAIT(1); } else { CP_WAIT(0); }
        __syncthreads();

        const int buf = s & 1;
        const uint32_t smA = smbase + buf * 8192;
        const uint32_t smW = smbase + 16384 + buf * 8192;

        #pragma unroll
        for (int kb2 = 0; kb2 < 128; kb2 += 32) {    // 4 k16 steps (bytes)
            uint32_t a0[4], a1[4], b0[2], b1[2];
            LDSM_X4(a0[0], a0[1], a0[2], a0[3], smA + arow0 + (((uint32_t)kb2 + acol) ^ swz));
            LDSM_X4(a1[0], a1[1], a1[2], a1[3], smA + arow1 + (((uint32_t)kb2 + acol) ^ swz));
            LDSM_X2(b0[0], b0[1], smW + brow0 + (((uint32_t)kb2 + bcol) ^ swz));
            LDSM_X2(b1[0], b1[1], smW + brow1 + (((uint32_t)kb2 + bcol) ^ swz));
            MMA16816(acc[0][0], a0, b0);
            MMA16816(acc[0][1], a0, b1);
            MMA16816(acc[1][0], a1, b0);
            MMA16816(acc[1][1], a1, b1);
        }
        __syncthreads();
        if (s + 2 < NSTAGE) { issue_stage(s + 2, buf); CP_COMMIT(); }
    }

    // epilogue: acc[mi][ni]: c0,c1 -> (row=lid/4, col=(lid%4)*2), c2,c3 -> row+8
    #pragma unroll
    for (int mi = 0; mi < 2; mi++) {
        #pragma unroll
        for (int ni = 0; ni < 2; ni++) {
            int r = m0 + wm * 32 + mi * 16 + (lid >> 2);
            int c = n0 + wn * 16 + ni * 8 + (lid & 3) * 2;
            float* base = &g_p2[((size_t)z * BATCH + r) * OUT_DIM + c];
            *reinterpret_cast<float2*>(base) =
                make_float2(acc[mi][ni][0], acc[mi][ni][1]);
            *reinterpret_cast<float2*>(base + 8 * OUT_DIM) =
                make_float2(acc[mi][ni][2], acc[mi][ni][3]);
        }
    }
}

// ---------------------------------------------------------------- reduce
__global__ void reduce_kernel(const float* __restrict__ bias_w,
                              float* __restrict__ out) {
    int idx = blockIdx.x * blockDim.x + threadIdx.x;   // float4 units
    if (idx >= BATCH * OUT_DIM / 4) return;
    int o4 = idx & 63;
    float4 r = reinterpret_cast<const float4*>(bias_w)[o4];
    const float4* p = reinterpret_cast<const float4*>(g_p2);
    #pragma unroll
    for (int zz = 0; zz < ZSPLIT; zz++) {
        float4 v = p[(size_t)zz * (BATCH * OUT_DIM / 4) + idx];
        r.x += v.x; r.y += v.y; r.z += v.z; r.w += v.w;
    }
    reinterpret_cast<float4*>(out)[idx] = r;
}

// ---------------------------------------------------------------- launch
extern "C" void kernel_launch(void* const* d_in, const int* in_sizes, int n_in,
                              void* d_out, int out_size) {
    const float* x          = (const float*)d_in[0];
    const float* grid       = (const float*)d_in[1];
    const float* coef       = (const float*)d_in[2];
    const float* scale_sp   = (const float*)d_in[3];
    const float* scale_base = (const float*)d_in[4];
    const float* bias_w     = (const float*)d_in[5];
    float* out = (float*)d_out;

    prep_w_kernel<<<(OUT_DIM * IN_DIM + 255) / 256, 256>>>(coef, scale_sp, scale_base);
    prep_a_kernel<<<(BATCH * IN_DIM + 255) / 256, 256>>>(x, grid);

    dim3 gdim(BATCH / TILE_M, OUT_DIM / TILE_N, ZSPLIT);   // (16, 4, 2) = 128 CTAs
    gemm_kernel<<<gdim, 256>>>();

    reduce_kernel<<<(BATCH * OUT_DIM / 4 + 255) / 256, 256>>>(bias_w, out);
}

// round 6
// speedup vs baseline: 2.7548x; 1.4435x over previous
#include <cuda_runtime.h>
#include <cuda_bf16.h>
#include <math.h>
#include <stdint.h>

// ---------------------------------------------------------------- constants
#define IN_DIM  128
#define OUT_DIM 256
#define NUM_F   8
#define BATCH   1024
#define KF      9
#define KDIM    1152                 // 128*9

#define TILE_M  64
#define TILE_N  64
#define BK      64                   // bf16 elems per k-chunk (128B rows)
#define ZSPLIT  2
#define STAGES  9                    // k-chunks per z half: 1152/64/2
#define STAGE_BYTES 32768            // Ah 8K + Al 8K + Wh 8K + Wl 8K
#define SMEM_BYTES  (3 * STAGE_BYTES)

// ---------------------------------------------------------------- scratch
__device__ __align__(16) __nv_bfloat16 g_Ah[BATCH * KDIM];
__device__ __align__(16) __nv_bfloat16 g_Al[BATCH * KDIM];
__device__ __align__(16) __nv_bfloat16 g_Wh[OUT_DIM * KDIM];
__device__ __align__(16) __nv_bfloat16 g_Wl[OUT_DIM * KDIM];

// ---------------------------------------------------------------- helpers
__device__ __forceinline__ uint32_t smem_u32(const void* p) {
    uint32_t a;
    asm("{ .reg .u64 t; cvta.to.shared.u64 t, %1; cvt.u32.u64 %0, t; }" : "=r"(a) : "l"(p));
    return a;
}
#define CP_ASYNC16(dst, src) \
    asm volatile("cp.async.cg.shared.global [%0], [%1], 16;" :: "r"(dst), "l"(src))
#define CP_COMMIT() asm volatile("cp.async.commit_group;" ::: "memory")
#define CP_WAIT(n)  asm volatile("cp.async.wait_group %0;" :: "n"(n) : "memory")

#define LDSM_X4(r, addr)                                                      \
    asm volatile("ldmatrix.sync.aligned.m8n8.x4.shared.b16 {%0,%1,%2,%3}, [%4];" \
                 : "=r"((r)[0]), "=r"((r)[1]), "=r"((r)[2]), "=r"((r)[3]) : "r"(addr))
#define LDSM_X2(r, addr)                                                      \
    asm volatile("ldmatrix.sync.aligned.m8n8.x2.shared.b16 {%0,%1}, [%2];"    \
                 : "=r"((r)[0]), "=r"((r)[1]) : "r"(addr))

#define MMA16816(c, a, b)                                                     \
    asm volatile("mma.sync.aligned.m16n8k16.row.col.f32.bf16.bf16.f32 "       \
                 "{%0,%1,%2,%3}, {%4,%5,%6,%7}, {%8,%9}, {%0,%1,%2,%3};"      \
                 : "+f"((c)[0]), "+f"((c)[1]), "+f"((c)[2]), "+f"((c)[3])     \
                 : "r"((a)[0]), "r"((a)[1]), "r"((a)[2]), "r"((a)[3]),        \
                   "r"((b)[0]), "r"((b)[1]))

// ---------------------------------------------------------------- fused prep
// blocks [0,128):    W pack + hi/lo split
// blocks [128,640):  A features + hi/lo split
// blocks [640,896):  out = bias (float4)
__global__ void prep_kernel(const float* __restrict__ x,
                            const float* __restrict__ grid,
                            const float* __restrict__ coef,
                            const float* __restrict__ scale_sp,
                            const float* __restrict__ scale_base,
                            const float* __restrict__ bias_w,
                            float* __restrict__ out) {
    const int blk = blockIdx.x;
    const int tid = threadIdx.x;

    if (blk < 128) {
        int n = blk * 256 + tid;                 // o*128 + i
        int o = n >> 7;
        int i = n & 127;
        float sp = scale_sp[n];
        float sb = scale_base[n];
        __nv_bfloat16* dh = &g_Wh[(size_t)o * KDIM + i * KF];
        __nv_bfloat16* dl = &g_Wl[(size_t)o * KDIM + i * KF];
        float4 c0 = reinterpret_cast<const float4*>(coef + (size_t)n * NUM_F)[0];
        float4 c1 = reinterpret_cast<const float4*>(coef + (size_t)n * NUM_F)[1];
        float v[KF] = {c0.x, c0.y, c0.z, c0.w, c1.x, c1.y, c1.z, c1.w, 0.0f};
        #pragma unroll
        for (int f = 0; f < NUM_F; f++) v[f] *= sp;
        v[NUM_F] = sb;
        #pragma unroll
        for (int f = 0; f < KF; f++) {
            __nv_bfloat16 hi = __float2bfloat16(v[f]);
            dh[f] = hi;
            dl[f] = __float2bfloat16(v[f] - __bfloat162float(hi));
        }
    } else if (blk < 640) {
        int idx = (blk - 128) * 256 + tid;       // b*128 + i
        float xv = x[idx];
        int b = idx >> 7;
        int i = idx & 127;
        __nv_bfloat16* dh = &g_Ah[(size_t)b * KDIM + i * KF];
        __nv_bfloat16* dl = &g_Al[(size_t)b * KDIM + i * KF];
        float vals[KF];
        #pragma unroll
        for (int f = 0; f < NUM_F; f++) vals[f] = __sinf(grid[f] * xv);
        vals[NUM_F] = xv / (1.0f + __expf(-xv));
        #pragma unroll
        for (int f = 0; f < KF; f++) {
            __nv_bfloat16 hi = __float2bfloat16(vals[f]);
            dh[f] = hi;
            dl[f] = __float2bfloat16(vals[f] - __bfloat162float(hi));
        }
    } else {
        int idx = (blk - 640) * 256 + tid;       // float4 units, 0..65535
        float4 v = reinterpret_cast<const float4*>(bias_w)[idx & 63];
        reinterpret_cast<float4*>(out)[idx] = v;
    }
}

// ---------------------------------------------------------------- GEMM
// grid (16, 4, 2).  Per k-chunk: load Ah/Al/Wh/Wl tiles once, accumulate
// Ah*Wh + Al*Wh + Ah*Wl into one fp32 acc set.  3-buffer cp.async pipeline,
// one barrier per stage.  Epilogue: RED.ADD into out (bias pre-written).
__global__ __launch_bounds__(256, 1) void gemm_kernel(float* __restrict__ out) {
    extern __shared__ __align__(128) uint8_t smem[];

    const int tid = threadIdx.x;
    const int wid = tid >> 5;
    const int lid = tid & 31;
    const int wm  = wid >> 2;          // 0..1 -> m rows wm*32
    const int wn  = wid & 3;           // 0..3 -> n cols wn*16
    const int m0  = blockIdx.x * TILE_M;
    const int n0  = blockIdx.y * TILE_N;
    const int z   = blockIdx.z;

    const uint32_t smbase = smem_u32(smem);

    // ldmatrix per-thread coords (proven R5 addressing)
    const uint32_t swz  = (uint32_t)((lid & 7) * 16);
    const uint32_t acol = (uint32_t)((lid >> 4) * 16);
    const uint32_t bcol = (uint32_t)(((lid >> 3) & 1) * 16);
    const uint32_t arow0 = (uint32_t)((wm * 32 + (lid & 15)) * 128);
    const uint32_t arow1 = arow0 + 16 * 128;
    const uint32_t brow0 = (uint32_t)((wn * 16 + (lid & 7)) * 128);
    const uint32_t brow1 = brow0 + 8 * 128;

    float acc[2][2][4];
    #pragma unroll
    for (int mi = 0; mi < 2; mi++)
        #pragma unroll
        for (int ni = 0; ni < 2; ni++)
            #pragma unroll
            for (int r = 0; r < 4; r++) acc[mi][ni][r] = 0.0f;

    // stage loader: 2048 x 16B -> 8 cp.async per thread
    // t: 0,1 -> Ah rows 0-31/32-63 ; 2,3 -> Al ; 4,5 -> Wh ; 6,7 -> Wl
    const int lrow = tid >> 3;                       // 0..31
    const int lc16 = tid & 7;
    const uint32_t lswz = (uint32_t)((lc16 * 16) ^ ((lrow & 7) * 16));

    auto issue_stage = [&](int s, int buf) {
        const int kofs = (z * STAGES + s) * BK;
        const uint32_t sb = smbase + buf * STAGE_BYTES;
        #pragma unroll
        for (int t = 0; t < 8; t++) {
            const int part = t >> 1;
            const int row  = (t & 1) * 32 + lrow;
            const uint32_t dst = sb + part * 8192 + (uint32_t)(row * 128) + lswz;
            const __nv_bfloat16* src;
            if (part == 0)      src = g_Ah + (size_t)(m0 + row) * KDIM;
            else if (part == 1) src = g_Al + (size_t)(m0 + row) * KDIM;
            else if (part == 2) src = g_Wh + (size_t)(n0 + row) * KDIM;
            else                src = g_Wl + (size_t)(n0 + row) * KDIM;
            CP_ASYNC16(dst, src + kofs + lc16 * 8);
        }
    };

    issue_stage(0, 0); CP_COMMIT();
    issue_stage(1, 1); CP_COMMIT();

    for (int s = 0; s < STAGES; s++) {
        if (s < STAGES - 2) { CP_WAIT(1); } else { CP_WAIT(0); }
        __syncthreads();
        if (s + 2 < STAGES) { issue_stage(s + 2, (s + 2) % 3); CP_COMMIT(); }

        const uint32_t sb = smbase + (s % 3) * STAGE_BYTES;
        const uint32_t smAh = sb;
        const uint32_t smAl = sb + 8192;
        const uint32_t smWh = sb + 16384;
        const uint32_t smWl = sb + 24576;

        #pragma unroll
        for (int kb2 = 0; kb2 < 128; kb2 += 32) {     // 4 k16 steps (bytes)
            const uint32_t ka = (((uint32_t)kb2 + acol) ^ swz);
            const uint32_t kb = (((uint32_t)kb2 + bcol) ^ swz);
            uint32_t ah0[4], ah1[4], al0[4], al1[4];
            uint32_t wh0[2], wh1[2], wl0[2], wl1[2];
            LDSM_X4(ah0, smAh + arow0 + ka);
            LDSM_X4(ah1, smAh + arow1 + ka);
            LDSM_X4(al0, smAl + arow0 + ka);
            LDSM_X4(al1, smAl + arow1 + ka);
            LDSM_X2(wh0, smWh + brow0 + kb);
            LDSM_X2(wh1, smWh + brow1 + kb);
            LDSM_X2(wl0, smWl + brow0 + kb);
            LDSM_X2(wl1, smWl + brow1 + kb);
            MMA16816(acc[0][0], ah0, wh0);
            MMA16816(acc[0][1], ah0, wh1);
            MMA16816(acc[1][0], ah1, wh0);
            MMA16816(acc[1][1], ah1, wh1);
            MMA16816(acc[0][0], al0, wh0);
            MMA16816(acc[0][1], al0, wh1);
            MMA16816(acc[1][0], al1, wh0);
            MMA16816(acc[1][1], al1, wh1);
            MMA16816(acc[0][0], ah0, wl0);
            MMA16816(acc[0][1], ah0, wl1);
            MMA16816(acc[1][0], ah1, wl0);
            MMA16816(acc[1][1], ah1, wl1);
        }
    }

    // epilogue: RED.ADD into out (bias already written by prep)
    #pragma unroll
    for (int mi = 0; mi < 2; mi++) {
        #pragma unroll
        for (int ni = 0; ni < 2; ni++) {
            int r = m0 + wm * 32 + mi * 16 + (lid >> 2);
            int c = n0 + wn * 16 + ni * 8 + (lid & 3) * 2;
            float* p = out + (size_t)r * OUT_DIM + c;
            atomicAdd(p,                    acc[mi][ni][0]);
            atomicAdd(p + 1,                acc[mi][ni][1]);
            atomicAdd(p + 8 * OUT_DIM,      acc[mi][ni][2]);
            atomicAdd(p + 8 * OUT_DIM + 1,  acc[mi][ni][3]);
        }
    }
}

// ---------------------------------------------------------------- launch
extern "C" void kernel_launch(void* const* d_in, const int* in_sizes, int n_in,
                              void* d_out, int out_size) {
    const float* x          = (const float*)d_in[0];
    const float* grid       = (const float*)d_in[1];
    const float* coef       = (const float*)d_in[2];
    const float* scale_sp   = (const float*)d_in[3];
    const float* scale_base = (const float*)d_in[4];
    const float* bias_w     = (const float*)d_in[5];
    float* out = (float*)d_out;

    // attribute set executes immediately (not a stream op) — capture-safe
    cudaFuncSetAttribute(gemm_kernel, cudaFuncAttributeMaxDynamicSharedMemorySize,
                         SMEM_BYTES);

    prep_kernel<<<896, 256>>>(x, grid, coef, scale_sp, scale_base, bias_w, out);

    dim3 gdim(BATCH / TILE_M, OUT_DIM / TILE_N, ZSPLIT);   // (16, 4, 2) = 128 CTAs
    gemm_kernel<<<gdim, 256, SMEM_BYTES>>>(out);
}

// round 7
// speedup vs baseline: 4.3103x; 1.5647x over previous
#include <cuda_runtime.h>
#include <cuda_bf16.h>
#include <math.h>
#include <stdint.h>

// ---------------------------------------------------------------- constants
#define IN_DIM  128
#define OUT_DIM 256
#define NUM_F   8
#define BATCH   1024
#define KF      9
#define KDIM    1152                 // 128*9

#define TILE_M  32
#define TILE_N  64
#define BK      64                   // bf16 elems per k-chunk (128B rows)
#define ZSPLIT  2
#define STAGES  9                    // 1152/64/2
// stage layout: Ah 4K @0, Al 4K @4096, Wh 8K @8192, Wl 8K @16384
#define STAGE_BYTES 24576
#define SMEM_BYTES  (3 * STAGE_BYTES)   // 73728

// ---------------------------------------------------------------- scratch
__device__ __align__(16) __nv_bfloat16 g_Ah[BATCH * KDIM];
__device__ __align__(16) __nv_bfloat16 g_Al[BATCH * KDIM];
__device__ __align__(16) __nv_bfloat16 g_Wh[OUT_DIM * KDIM];
__device__ __align__(16) __nv_bfloat16 g_Wl[OUT_DIM * KDIM];

// ---------------------------------------------------------------- helpers
__device__ __forceinline__ uint32_t smem_u32(const void* p) {
    uint32_t a;
    asm("{ .reg .u64 t; cvta.to.shared.u64 t, %1; cvt.u32.u64 %0, t; }" : "=r"(a) : "l"(p));
    return a;
}
#define CP_ASYNC16(dst, src) \
    asm volatile("cp.async.cg.shared.global [%0], [%1], 16;" :: "r"(dst), "l"(src))
#define CP_COMMIT() asm volatile("cp.async.commit_group;" ::: "memory")
#define CP_WAIT(n)  asm volatile("cp.async.wait_group %0;" :: "n"(n) : "memory")

#define LDSM_X4(r, addr)                                                      \
    asm volatile("ldmatrix.sync.aligned.m8n8.x4.shared.b16 {%0,%1,%2,%3}, [%4];" \
                 : "=r"((r)[0]), "=r"((r)[1]), "=r"((r)[2]), "=r"((r)[3]) : "r"(addr))

#define MMA16816(c, a, b0, b1)                                                \
    asm volatile("mma.sync.aligned.m16n8k16.row.col.f32.bf16.bf16.f32 "       \
                 "{%0,%1,%2,%3}, {%4,%5,%6,%7}, {%8,%9}, {%0,%1,%2,%3};"      \
                 : "+f"((c)[0]), "+f"((c)[1]), "+f"((c)[2]), "+f"((c)[3])     \
                 : "r"((a)[0]), "r"((a)[1]), "r"((a)[2]), "r"((a)[3]),        \
                   "r"(b0), "r"(b1))

// ---------------------------------------------------------------- fused prep
// blocks [0,128):    W pack + hi/lo split (2 o-rows per block, smem staged)
// blocks [128,640):  A features + hi/lo split (2 b-rows per block, smem staged)
// blocks [640,896):  out = bias (float4)
__global__ void prep_kernel(const float* __restrict__ x,
                            const float* __restrict__ grid,
                            const float* __restrict__ coef,
                            const float* __restrict__ scale_sp,
                            const float* __restrict__ scale_base,
                            const float* __restrict__ bias_w,
                            float* __restrict__ out) {
    __shared__ __align__(16) __nv_bfloat16 sh_hi[2 * KDIM];   // 4608B
    __shared__ __align__(16) __nv_bfloat16 sh_lo[2 * KDIM];

    const int blk = blockIdx.x;
    const int tid = threadIdx.x;

    if (blk >= 640) {                        // bias init
        int idx = (blk - 640) * 256 + tid;   // float4 units
        float4 v = reinterpret_cast<const float4*>(bias_w)[idx & 63];
        reinterpret_cast<float4*>(out)[idx] = v;
        return;
    }

    float vals[KF];
    __nv_bfloat16* gdst_h;
    __nv_bfloat16* gdst_l;

    if (blk < 128) {                         // ---- W pack
        int n = blk * 256 + tid;             // o*128 + i
        float sp = scale_sp[n];
        float4 c0 = reinterpret_cast<const float4*>(coef + (size_t)n * NUM_F)[0];
        float4 c1 = reinterpret_cast<const float4*>(coef + (size_t)n * NUM_F)[1];
        vals[0] = c0.x * sp; vals[1] = c0.y * sp; vals[2] = c0.z * sp; vals[3] = c0.w * sp;
        vals[4] = c1.x * sp; vals[5] = c1.y * sp; vals[6] = c1.z * sp; vals[7] = c1.w * sp;
        vals[8] = scale_base[n];
        gdst_h = g_Wh + (size_t)blk * 2 * KDIM;
        gdst_l = g_Wl + (size_t)blk * 2 * KDIM;
    } else {                                 // ---- A features
        int idx = (blk - 128) * 256 + tid;   // b*128 + i
        float xv = x[idx];
        // sin(k*x), k=1..8 via Chebyshev recurrence: 2 MUFU instead of 8
        float s1, c1v;
        s1  = __sinf(xv);
        c1v = __cosf(xv);
        float two_c = 2.0f * c1v;
        float sm1 = 0.0f, sk = s1;
        vals[0] = s1;
        #pragma unroll
        for (int f = 1; f < NUM_F; f++) {
            float sn = two_c * sk - sm1;
            vals[f] = sn;
            sm1 = sk;
            sk = sn;
        }
        vals[NUM_F] = xv * (1.0f / (1.0f + __expf(-xv)));   // silu
        gdst_h = g_Ah + (size_t)(blk - 128) * 2 * KDIM;
        gdst_l = g_Al + (size_t)(blk - 128) * 2 * KDIM;
    }

    // stage hi/lo into smem (local row = tid>>7, col = (tid&127)*9)
    {
        int lofs = (tid >> 7) * KDIM + (tid & 127) * KF;
        #pragma unroll
        for (int f = 0; f < KF; f++) {
            __nv_bfloat16 hi = __float2bfloat16(vals[f]);
            sh_hi[lofs + f] = hi;
            sh_lo[lofs + f] = __float2bfloat16(vals[f] - __bfloat162float(hi));
        }
    }
    __syncthreads();

    // coalesced flush: 2*KDIM bf16 = 288 uint4 per array
    for (int u = tid; u < 288; u += 256) {
        reinterpret_cast<uint4*>(gdst_h)[u] = reinterpret_cast<const uint4*>(sh_hi)[u];
        reinterpret_cast<uint4*>(gdst_l)[u] = reinterpret_cast<const uint4*>(sh_lo)[u];
    }
}

// ---------------------------------------------------------------- GEMM
// grid (32, 4, 2) = 256 CTAs, 2 per SM.  Warp grid 2x4, warp tile 16x16.
// Per k-chunk: Ah/Al/Wh/Wl loaded once; acc += Ah*Wh + Al*Wh + Ah*Wl.
// 3-buffer cp.async pipeline, 1 barrier/stage.  Epilogue RED.ADD (bias prewritten).
__global__ __launch_bounds__(256, 2) void gemm_kernel(float* __restrict__ out) {
    extern __shared__ __align__(128) uint8_t smem[];

    const int tid = threadIdx.x;
    const int wid = tid >> 5;
    const int lid = tid & 31;
    const int wm  = wid >> 2;          // 0..1 -> m rows wm*16
    const int wn  = wid & 3;           // 0..3 -> n cols wn*16
    const int m0  = blockIdx.x * TILE_M;
    const int n0  = blockIdx.y * TILE_N;
    const int z   = blockIdx.z;

    const uint32_t smbase = smem_u32(smem);

    // ldmatrix addressing (R5-proven pattern)
    const uint32_t swz  = (uint32_t)((lid & 7) * 16);
    const uint32_t acol = (uint32_t)((lid >> 4) * 16);                 // A k-half
    const uint32_t arow = (uint32_t)((wm * 16 + (lid & 15)) * 128);
    // B x4: lanes 0-15 -> n rows +0..7 (k halves), lanes 16-31 -> n rows +8..15
    const uint32_t bcol = (uint32_t)(((lid >> 3) & 1) * 16);
    const uint32_t brow = (uint32_t)((wn * 16 + (lid >> 4) * 8 + (lid & 7)) * 128);

    float acc[2][4];
    #pragma unroll
    for (int ni = 0; ni < 2; ni++)
        #pragma unroll
        for (int r = 0; r < 4; r++) acc[ni][r] = 0.0f;

    // stage loader: 1536 x 16B -> 6 cp.async per thread
    const int lrow = tid >> 3;                       // 0..31
    const int lc16 = tid & 7;
    const uint32_t lswz = (uint32_t)((lc16 * 16) ^ ((lrow & 7) * 16));

    auto issue_stage = [&](int s, int buf) {
        const int kofs = (z * STAGES + s) * BK + lc16 * 8;
        const uint32_t sb = smbase + buf * STAGE_BYTES;
        const uint32_t rb = (uint32_t)(lrow * 128) + lswz;
        CP_ASYNC16(sb + rb,                 g_Ah + (size_t)(m0 + lrow) * KDIM + kofs);
        CP_ASYNC16(sb + 4096 + rb,          g_Al + (size_t)(m0 + lrow) * KDIM + kofs);
        CP_ASYNC16(sb + 8192 + rb,          g_Wh + (size_t)(n0 + lrow) * KDIM + kofs);
        CP_ASYNC16(sb + 8192 + 4096 + rb,   g_Wh + (size_t)(n0 + lrow + 32) * KDIM + kofs);
        CP_ASYNC16(sb + 16384 + rb,         g_Wl + (size_t)(n0 + lrow) * KDIM + kofs);
        CP_ASYNC16(sb + 16384 + 4096 + rb,  g_Wl + (size_t)(n0 + lrow + 32) * KDIM + kofs);
    };

    issue_stage(0, 0); CP_COMMIT();
    issue_stage(1, 1); CP_COMMIT();

    for (int s = 0; s < STAGES; s++) {
        if (s < STAGES - 2) { CP_WAIT(1); } else { CP_WAIT(0); }
        __syncthreads();
        if (s + 2 < STAGES) { issue_stage(s + 2, (s + 2) % 3); CP_COMMIT(); }

        const uint32_t sb = smbase + (s % 3) * STAGE_BYTES;

        #pragma unroll
        for (int kb2 = 0; kb2 < 128; kb2 += 32) {     // 4 k16 steps (bytes)
            const uint32_t ka = ((uint32_t)kb2 + acol) ^ swz;
            const uint32_t kb = ((uint32_t)kb2 + bcol) ^ swz;
            uint32_t ah[4], al[4], wh[4], wl[4];
            LDSM_X4(ah, sb + arow + ka);
            LDSM_X4(al, sb + 4096 + arow + ka);
            LDSM_X4(wh, sb + 8192 + brow + kb);
            LDSM_X4(wl, sb + 16384 + brow + kb);
            MMA16816(acc[0], ah, wh[0], wh[1]);
            MMA16816(acc[1], ah, wh[2], wh[3]);
            MMA16816(acc[0], al, wh[0], wh[1]);
            MMA16816(acc[1], al, wh[2], wh[3]);
            MMA16816(acc[0], ah, wl[0], wl[1]);
            MMA16816(acc[1], ah, wl[2], wl[3]);
        }
    }

    // epilogue: RED.ADD into out (bias already written by prep)
    {
        int r = m0 + wm * 16 + (lid >> 2);
        #pragma unroll
        for (int ni = 0; ni < 2; ni++) {
            int c = n0 + wn * 16 + ni * 8 + (lid & 3) * 2;
            float* p = out + (size_t)r * OUT_DIM + c;
            atomicAdd(p,                    acc[ni][0]);
            atomicAdd(p + 1,                acc[ni][1]);
            atomicAdd(p + 8 * OUT_DIM,      acc[ni][2]);
            atomicAdd(p + 8 * OUT_DIM + 1,  acc[ni][3]);
        }
    }
}

// ---------------------------------------------------------------- launch
extern "C" void kernel_launch(void* const* d_in, const int* in_sizes, int n_in,
                              void* d_out, int out_size) {
    const float* x          = (const float*)d_in[0];
    const float* grid       = (const float*)d_in[1];
    const float* coef       = (const float*)d_in[2];
    const float* scale_sp   = (const float*)d_in[3];
    const float* scale_base = (const float*)d_in[4];
    const float* bias_w     = (const float*)d_in[5];
    float* out = (float*)d_out;

    cudaFuncSetAttribute(gemm_kernel, cudaFuncAttributeMaxDynamicSharedMemorySize,
                         SMEM_BYTES);

    prep_kernel<<<896, 256>>>(x, grid, coef, scale_sp, scale_base, bias_w, out);

    dim3 gdim(BATCH / TILE_M, OUT_DIM / TILE_N, ZSPLIT);   // (32, 4, 2) = 256 CTAs
    gemm_kernel<<<gdim, 256, SMEM_BYTES>>>(out);
}

// round 9
// speedup vs baseline: 4.3197x; 1.0022x over previous
#include <cuda_runtime.h>
#include <cuda_fp16.h>
#include <math.h>
#include <stdint.h>

// ---------------------------------------------------------------- constants
#define IN_DIM  128
#define OUT_DIM 256
#define NUM_F   8
#define BATCH   1024
#define KF      9
#define KDIM    1152                 // 128*9

#define TILE_M  32
#define TILE_N  64
#define BK      64                   // fp16 elems per k-chunk (128B rows)
#define ZSPLIT  4
#define NCHUNK  18                   // 1152/64
// stage layout: Ah 4K @0, Al 4K @4096, Wh 8K @8192
#define STAGE_BYTES 16384
#define SMEM_BYTES  (3 * STAGE_BYTES)   // 49152

// ---------------------------------------------------------------- scratch
__device__ __align__(16) __half g_Ah[BATCH * KDIM];
__device__ __align__(16) __half g_Al[BATCH * KDIM];
__device__ __align__(16) __half g_Wh[OUT_DIM * KDIM];

// ---------------------------------------------------------------- helpers
__device__ __forceinline__ uint32_t smem_u32(const void* p) {
    uint32_t a;
    asm("{ .reg .u64 t; cvta.to.shared.u64 t, %1; cvt.u32.u64 %0, t; }" : "=r"(a) : "l"(p));
    return a;
}
#define CP_ASYNC16(dst, src) \
    asm volatile("cp.async.cg.shared.global [%0], [%1], 16;" :: "r"(dst), "l"(src))
#define CP_COMMIT() asm volatile("cp.async.commit_group;" ::: "memory")
#define CP_WAIT(n)  asm volatile("cp.async.wait_group %0;" :: "n"(n) : "memory")

#define LDSM_X4(r, addr)                                                      \
    asm volatile("ldmatrix.sync.aligned.m8n8.x4.shared.b16 {%0,%1,%2,%3}, [%4];" \
                 : "=r"((r)[0]), "=r"((r)[1]), "=r"((r)[2]), "=r"((r)[3]) : "r"(addr))

#define MMA16816F16(c, a, b0, b1)                                             \
    asm volatile("mma.sync.aligned.m16n8k16.row.col.f32.f16.f16.f32 "         \
                 "{%0,%1,%2,%3}, {%4,%5,%6,%7}, {%8,%9}, {%0,%1,%2,%3};"      \
                 : "+f"((c)[0]), "+f"((c)[1]), "+f"((c)[2]), "+f"((c)[3])     \
                 : "r"((a)[0]), "r"((a)[1]), "r"((a)[2]), "r"((a)[3]),        \
                   "r"(b0), "r"(b1))

// ---------------------------------------------------------------- fused prep
// blocks [0,128):    W pack -> fp16 (2 o-rows per block, smem staged)
// blocks [128,640):  A features -> fp16 hi/lo (2 b-rows per block, smem staged)
// blocks [640,896):  out = bias (float4)
__global__ void prep_kernel(const float* __restrict__ x,
                            const float* __restrict__ grid,
                            const float* __restrict__ coef,
                            const float* __restrict__ scale_sp,
                            const float* __restrict__ scale_base,
                            const float* __restrict__ bias_w,
                            float* __restrict__ out) {
    __shared__ __align__(16) __half sh_hi[2 * KDIM];   // 4608B
    __shared__ __align__(16) __half sh_lo[2 * KDIM];

    const int blk = blockIdx.x;
    const int tid = threadIdx.x;

    if (blk >= 640) {                        // bias init
        int idx = (blk - 640) * 256 + tid;   // float4 units
        float4 v = reinterpret_cast<const float4*>(bias_w)[idx & 63];
        reinterpret_cast<float4*>(out)[idx] = v;
        return;
    }

    float vals[KF];

    if (blk < 128) {                         // ---- W pack (fp16 only)
        int n = blk * 256 + tid;             // o*128 + i
        float sp = scale_sp[n];
        float4 c0 = reinterpret_cast<const float4*>(coef + (size_t)n * NUM_F)[0];
        float4 c1 = reinterpret_cast<const float4*>(coef + (size_t)n * NUM_F)[1];
        vals[0] = c0.x * sp; vals[1] = c0.y * sp; vals[2] = c0.z * sp; vals[3] = c0.w * sp;
        vals[4] = c1.x * sp; vals[5] = c1.y * sp; vals[6] = c1.z * sp; vals[7] = c1.w * sp;
        vals[8] = scale_base[n];
        int lofs = (tid >> 7) * KDIM + (tid & 127) * KF;
        #pragma unroll
        for (int f = 0; f < KF; f++) sh_hi[lofs + f] = __float2half(vals[f]);
        __syncthreads();
        __half* gdst = g_Wh + (size_t)blk * 2 * KDIM;
        for (int u = tid; u < 288; u += 256)
            reinterpret_cast<uint4*>(gdst)[u] = reinterpret_cast<const uint4*>(sh_hi)[u];
        return;
    }

    // ---- A features (fp16 hi + lo)
    {
        int idx = (blk - 128) * 256 + tid;   // b*128 + i
        float xv = x[idx];
        // sin(k*x), k=1..8 via Chebyshev recurrence: 2 MUFU instead of 8
        float s1  = __sinf(xv);
        float c1v = __cosf(xv);
        float two_c = 2.0f * c1v;
        float sm1 = 0.0f, sk = s1;
        vals[0] = s1;
        #pragma unroll
        for (int f = 1; f < NUM_F; f++) {
            float sn = two_c * sk - sm1;
            vals[f] = sn;
            sm1 = sk;
            sk = sn;
        }
        vals[NUM_F] = xv * (1.0f / (1.0f + __expf(-xv)));   // silu

        int lofs = (tid >> 7) * KDIM + (tid & 127) * KF;
        #pragma unroll
        for (int f = 0; f < KF; f++) {
            __half hi = __float2half(vals[f]);
            sh_hi[lofs + f] = hi;
            sh_lo[lofs + f] = __float2half(vals[f] - __half2float(hi));
        }
        __syncthreads();
        __half* gh = g_Ah + (size_t)(blk - 128) * 2 * KDIM;
        __half* gl = g_Al + (size_t)(blk - 128) * 2 * KDIM;
        for (int u = tid; u < 288; u += 256) {
            reinterpret_cast<uint4*>(gh)[u] = reinterpret_cast<const uint4*>(sh_hi)[u];
            reinterpret_cast<uint4*>(gl)[u] = reinterpret_cast<const uint4*>(sh_lo)[u];
        }
    }
}

// ---------------------------------------------------------------- GEMM
// grid (32, 4, 4) = 512 CTAs.  Warp grid 2x4, warp tile 16x16.
// acc += Ah*Wh + Al*Wh  (fp16 inputs, fp32 accum).  z-chunks: 5/5/4/4 of 18.
// 3-buffer cp.async pipeline, 1 barrier/stage.  Epilogue RED.ADD (bias prewritten).
__global__ __launch_bounds__(256, 2) void gemm_kernel(float* __restrict__ out) {
    extern __shared__ __align__(128) uint8_t smem[];

    const int tid = threadIdx.x;
    const int wid = tid >> 5;
    const int lid = tid & 31;
    const int wm  = wid >> 2;          // 0..1 -> m rows wm*16
    const int wn  = wid & 3;           // 0..3 -> n cols wn*16
    const int m0  = blockIdx.x * TILE_M;
    const int n0  = blockIdx.y * TILE_N;
    const int z   = blockIdx.z;

    // chunk range for this z: z0 [0,5) z1 [5,10) z2 [10,14) z3 [14,18)
    const int c0     = z * 4 + ((z < 2) ? z : 2);
    const int scount = (z < 2) ? 5 : 4;

    const uint32_t smbase = smem_u32(smem);

    // ldmatrix addressing (proven pattern)
    const uint32_t swz  = (uint32_t)((lid & 7) * 16);
    const uint32_t acol = (uint32_t)((lid >> 4) * 16);
    const uint32_t arow = (uint32_t)((wm * 16 + (lid & 15)) * 128);
    const uint32_t bcol = (uint32_t)(((lid >> 3) & 1) * 16);
    const uint32_t brow = (uint32_t)((wn * 16 + (lid >> 4) * 8 + (lid & 7)) * 128);

    float acc[2][4];
    #pragma unroll
    for (int ni = 0; ni < 2; ni++)
        #pragma unroll
        for (int r = 0; r < 4; r++) acc[ni][r] = 0.0f;

    // stage loader: 1024 x 16B -> 4 cp.async per thread
    const int lrow = tid >> 3;                       // 0..31
    const int lc16 = tid & 7;
    const uint32_t lswz = (uint32_t)((lc16 * 16) ^ ((lrow & 7) * 16));

    auto issue_stage = [&](int s, int buf) {
        const int kofs = (c0 + s) * BK + lc16 * 8;
        const uint32_t sb = smbase + buf * STAGE_BYTES;
        const uint32_t rb = (uint32_t)(lrow * 128) + lswz;
        CP_ASYNC16(sb + rb,                g_Ah + (size_t)(m0 + lrow) * KDIM + kofs);
        CP_ASYNC16(sb + 4096 + rb,         g_Al + (size_t)(m0 + lrow) * KDIM + kofs);
        CP_ASYNC16(sb + 8192 + rb,         g_Wh + (size_t)(n0 + lrow) * KDIM + kofs);
        CP_ASYNC16(sb + 8192 + 4096 + rb,  g_Wh + (size_t)(n0 + lrow + 32) * KDIM + kofs);
    };

    issue_stage(0, 0); CP_COMMIT();
    issue_stage(1, 1); CP_COMMIT();

    for (int s = 0; s < scount; s++) {
        if (s < scount - 2) { CP_WAIT(1); } else { CP_WAIT(0); }
        __syncthreads();
        if (s + 2 < scount) { issue_stage(s + 2, (s + 2) % 3); CP_COMMIT(); }

        const uint32_t sb = smbase + (s % 3) * STAGE_BYTES;

        #pragma unroll
        for (int kb2 = 0; kb2 < 128; kb2 += 32) {     // 4 k16 steps (bytes)
            const uint32_t ka = ((uint32_t)kb2 + acol) ^ swz;
            const uint32_t kb = ((uint32_t)kb2 + bcol) ^ swz;
            uint32_t ah[4], al[4], wh[4];
            LDSM_X4(ah, sb + arow + ka);
            LDSM_X4(al, sb + 4096 + arow + ka);
            LDSM_X4(wh, sb + 8192 + brow + kb);
            MMA16816F16(acc[0], ah, wh[0], wh[1]);
            MMA16816F16(acc[1], ah, wh[2], wh[3]);
            MMA16816F16(acc[0], al, wh[0], wh[1]);
            MMA16816F16(acc[1], al, wh[2], wh[3]);
        }
    }

    // epilogue: RED.ADD into out (bias already written by prep)
    {
        int r = m0 + wm * 16 + (lid >> 2);
        #pragma unroll
        for (int ni = 0; ni < 2; ni++) {
            int c = n0 + wn * 16 + ni * 8 + (lid & 3) * 2;
            float* p = out + (size_t)r * OUT_DIM + c;
            atomicAdd(p,                    acc[ni][0]);
            atomicAdd(p + 1,                acc[ni][1]);
            atomicAdd(p + 8 * OUT_DIM,      acc[ni][2]);
            atomicAdd(p + 8 * OUT_DIM + 1,  acc[ni][3]);
        }
    }
}

// ---------------------------------------------------------------- launch
extern "C" void kernel_launch(void* const* d_in, const int* in_sizes, int n_in,
                              void* d_out, int out_size) {
    const float* x          = (const float*)d_in[0];
    const float* grid       = (const float*)d_in[1];
    const float* coef       = (const float*)d_in[2];
    const float* scale_sp   = (const float*)d_in[3];
    const float* scale_base = (const float*)d_in[4];
    const float* bias_w     = (const float*)d_in[5];
    float* out = (float*)d_out;

    cudaFuncSetAttribute(gemm_kernel, cudaFuncAttributeMaxDynamicSharedMemorySize,
                         SMEM_BYTES);

    prep_kernel<<<896, 256>>>(x, grid, coef, scale_sp, scale_base, bias_w, out);

    dim3 gdim(BATCH / TILE_M, OUT_DIM / TILE_N, ZSPLIT);   // (32, 4, 4) = 512 CTAs
    gemm_kernel<<<gdim, 256, SMEM_BYTES>>>(out);
}

// round 13
// speedup vs baseline: 5.8309x; 1.3499x over previous
#include <cuda_runtime.h>
#include <cuda_fp16.h>
#include <math.h>
#include <stdint.h>

// ---------------------------------------------------------------- constants
#define IN_DIM  128
#define OUT_DIM 256
#define NUM_F   8
#define BATCH   1024
#define KF      9
#define KDIM    1152                 // 128*9

#define TILE_M  64
#define TILE_N  64
#define BK      64                   // fp16 elems per k-chunk (128B rows)
#define ZSPLIT  4
// stage layout: A 8K @0, W 8K @8192
#define STAGE_BYTES 16384
#define SMEM_BYTES  (3 * STAGE_BYTES)   // 49152

// ---------------------------------------------------------------- scratch
__device__ __align__(16) __half g_A[BATCH * KDIM];
__device__ __align__(16) __half g_W[OUT_DIM * KDIM];

// ---------------------------------------------------------------- helpers
__device__ __forceinline__ uint32_t smem_u32(const void* p) {
    uint32_t a;
    asm("{ .reg .u64 t; cvta.to.shared.u64 t, %1; cvt.u32.u64 %0, t; }" : "=r"(a) : "l"(p));
    return a;
}
#define CP_ASYNC16(dst, src) \
    asm volatile("cp.async.cg.shared.global [%0], [%1], 16;" :: "r"(dst), "l"(src))
#define CP_COMMIT() asm volatile("cp.async.commit_group;" ::: "memory")
#define CP_WAIT(n)  asm volatile("cp.async.wait_group %0;" :: "n"(n) : "memory")

#define LDSM_X4(r, addr)                                                      \
    asm volatile("ldmatrix.sync.aligned.m8n8.x4.shared.b16 {%0,%1,%2,%3}, [%4];" \
                 : "=r"((r)[0]), "=r"((r)[1]), "=r"((r)[2]), "=r"((r)[3]) : "r"(addr))

#define MMA16816F16(c, a, b0, b1)                                             \
    asm volatile("mma.sync.aligned.m16n8k16.row.col.f32.f16.f16.f32 "         \
                 "{%0,%1,%2,%3}, {%4,%5,%6,%7}, {%8,%9}, {%0,%1,%2,%3};"      \
                 : "+f"((c)[0]), "+f"((c)[1]), "+f"((c)[2]), "+f"((c)[3])     \
                 : "r"((a)[0]), "r"((a)[1]), "r"((a)[2]), "r"((a)[3]),        \
                   "r"(b0), "r"(b1))

// ---------------------------------------------------------------- fused prep
// blocks [0,128):    W pack -> fp16 (2 o-rows per block, smem staged)
// blocks [128,640):  A features -> fp16 (2 b-rows per block, smem staged)
// blocks [640,896):  out = bias (float4)
__global__ void prep_kernel(const float* __restrict__ x,
                            const float* __restrict__ grid,
                            const float* __restrict__ coef,
                            const float* __restrict__ scale_sp,
                            const float* __restrict__ scale_base,
                            const float* __restrict__ bias_w,
                            float* __restrict__ out) {
    __shared__ __align__(16) __half sh[2 * KDIM];   // 4608B

    const int blk = blockIdx.x;
    const int tid = threadIdx.x;

    if (blk >= 640) {                        // bias init
        int idx = (blk - 640) * 256 + tid;   // float4 units
        float4 v = reinterpret_cast<const float4*>(bias_w)[idx & 63];
        reinterpret_cast<float4*>(out)[idx] = v;
        return;
    }

    float vals[KF];
    __half* gdst;

    if (blk < 128) {                         // ---- W pack (fp16)
        int n = blk * 256 + tid;             // o*128 + i
        float sp = scale_sp[n];
        float4 c0 = reinterpret_cast<const float4*>(coef + (size_t)n * NUM_F)[0];
        float4 c1 = reinterpret_cast<const float4*>(coef + (size_t)n * NUM_F)[1];
        vals[0] = c0.x * sp; vals[1] = c0.y * sp; vals[2] = c0.z * sp; vals[3] = c0.w * sp;
        vals[4] = c1.x * sp; vals[5] = c1.y * sp; vals[6] = c1.z * sp; vals[7] = c1.w * sp;
        vals[8] = scale_base[n];
        gdst = g_W + (size_t)blk * 2 * KDIM;
    } else {                                 // ---- A features
        int idx = (blk - 128) * 256 + tid;   // b*128 + i
        float xv = x[idx];
        // sin(k*x), k=1..8 via Chebyshev recurrence: 2 MUFU instead of 8
        float s1  = __sinf(xv);
        float c1v = __cosf(xv);
        float two_c = 2.0f * c1v;
        float sm1 = 0.0f, sk = s1;
        vals[0] = s1;
        #pragma unroll
        for (int f = 1; f < NUM_F; f++) {
            float sn = two_c * sk - sm1;
            vals[f] = sn;
            sm1 = sk;
            sk = sn;
        }
        vals[NUM_F] = xv * (1.0f / (1.0f + __expf(-xv)));   // silu
        gdst = g_A + (size_t)(blk - 128) * 2 * KDIM;
    }

    // stage into smem (local row = tid>>7, col = (tid&127)*9), coalesced flush
    {
        int lofs = (tid >> 7) * KDIM + (tid & 127) * KF;
        #pragma unroll
        for (int f = 0; f < KF; f++) sh[lofs + f] = __float2half(vals[f]);
    }
    __syncthreads();
    for (int u = tid; u < 288; u += 256)
        reinterpret_cast<uint4*>(gdst)[u] = reinterpret_cast<const uint4*>(sh)[u];
}

// ---------------------------------------------------------------- GEMM
// grid (16, 4, 4) = 256 CTAs, 128 threads (4 warps, 2x2), warp tile 32x32.
// Single fp16 GEMM: acc += A*W^T.  Per kstep: 4 LDSM.x4 -> 8 independent MMAs
// (dep distance 8).  z-chunks 5/5/4/4 of 18.  3-buffer cp.async pipeline.
// Epilogue RED.ADD into out (bias prewritten by prep).
__global__ __launch_bounds__(128, 4) void gemm_kernel(float* __restrict__ out) {
    extern __shared__ __align__(128) uint8_t smem[];

    const int tid = threadIdx.x;
    const int wid = tid >> 5;
    const int lid = tid & 31;
    const int wm  = wid >> 1;          // 0..1 -> m rows wm*32
    const int wn  = wid & 1;           // 0..1 -> n cols wn*32
    const int m0  = blockIdx.x * TILE_M;
    const int n0  = blockIdx.y * TILE_N;
    const int z   = blockIdx.z;

    // chunk range: z0 [0,5) z1 [5,10) z2 [10,14) z3 [14,18)
    const int c0     = (z < 2) ? z * 5 : 10 + (z - 2) * 4;
    const int scount = (z < 2) ? 5 : 4;

    const uint32_t smbase = smem_u32(smem);

    // ldmatrix addressing (proven pattern)
    const uint32_t swz   = (uint32_t)((lid & 7) * 16);
    const uint32_t acol  = (uint32_t)((lid >> 4) * 16);
    const uint32_t arow0 = (uint32_t)((wm * 32 + (lid & 15)) * 128);
    const uint32_t arow1 = arow0 + 16 * 128;
    const uint32_t bcol  = (uint32_t)(((lid >> 3) & 1) * 16);
    const uint32_t brow0 = (uint32_t)((wn * 32 + (lid >> 4) * 8 + (lid & 7)) * 128);
    const uint32_t brow1 = brow0 + 16 * 128;

    float acc[2][4][4];
    #pragma unroll
    for (int j = 0; j < 2; j++)
        #pragma unroll
        for (int q = 0; q < 4; q++)
            #pragma unroll
            for (int r = 0; r < 4; r++) acc[j][q][r] = 0.0f;

    // stage loader: 1024 x 16B -> 8 cp.async per thread (4 A rows + 4 W rows)
    const int lrow = tid >> 3;                       // 0..15
    const int lc16 = tid & 7;
    const uint32_t lswz = (uint32_t)((lc16 * 16) ^ ((lrow & 7) * 16));

    auto issue_stage = [&](int s, int buf) {
        const int kofs = (c0 + s) * BK + lc16 * 8;
        const uint32_t sb = smbase + buf * STAGE_BYTES;
        #pragma unroll
        for (int t = 0; t < 4; t++) {
            const int row = lrow + t * 16;
            const uint32_t rb = (uint32_t)(row * 128) + lswz;
            CP_ASYNC16(sb + rb,        g_A + (size_t)(m0 + row) * KDIM + kofs);
            CP_ASYNC16(sb + 8192 + rb, g_W + (size_t)(n0 + row) * KDIM + kofs);
        }
    };

    issue_stage(0, 0); CP_COMMIT();
    issue_stage(1, 1); CP_COMMIT();

    for (int s = 0; s < scount; s++) {
        if (s < scount - 2) { CP_WAIT(1); } else { CP_WAIT(0); }
        __syncthreads();
        if (s + 2 < scount) { issue_stage(s + 2, (s + 2) % 3); CP_COMMIT(); }

        const uint32_t sb = smbase + (s % 3) * STAGE_BYTES;

        #pragma unroll
        for (int kb2 = 0; kb2 < 128; kb2 += 32) {     // 4 k16 steps (bytes)
            const uint32_t ka = ((uint32_t)kb2 + acol) ^ swz;
            const uint32_t kb = ((uint32_t)kb2 + bcol) ^ swz;
            uint32_t a0[4], a1[4], w0[4], w1[4];
            LDSM_X4(a0, sb + arow0 + ka);
            LDSM_X4(a1, sb + arow1 + ka);
            LDSM_X4(w0, sb + 8192 + brow0 + kb);
            LDSM_X4(w1, sb + 8192 + brow1 + kb);
            // 8 independent MMAs
            MMA16816F16(acc[0][0], a0, w0[0], w0[1]);
            MMA16816F16(acc[0][1], a0, w0[2], w0[3]);
            MMA16816F16(acc[0][2], a0, w1[0], w1[1]);
            MMA16816F16(acc[0][3], a0, w1[2], w1[3]);
            MMA16816F16(acc[1][0], a1, w0[0], w0[1]);
            MMA16816F16(acc[1][1], a1, w0[2], w0[3]);
            MMA16816F16(acc[1][2], a1, w1[0], w1[1]);
            MMA16816F16(acc[1][3], a1, w1[2], w1[3]);
        }
    }

    // epilogue: RED.ADD into out (bias already written by prep)
    #pragma unroll
    for (int j = 0; j < 2; j++) {
        int r = m0 + wm * 32 + j * 16 + (lid >> 2);
        #pragma unroll
        for (int q = 0; q < 4; q++) {
            int c = n0 + wn * 32 + q * 8 + (lid & 3) * 2;
            float* p = out + (size_t)r * OUT_DIM + c;
            atomicAdd(p,                    acc[j][q][0]);
            atomicAdd(p + 1,                acc[j][q][1]);
            atomicAdd(p + 8 * OUT_DIM,      acc[j][q][2]);
            atomicAdd(p + 8 * OUT_DIM + 1,  acc[j][q][3]);
        }
    }
}

// ---------------------------------------------------------------- launch
extern "C" void kernel_launch(void* const* d_in, const int* in_sizes, int n_in,
                              void* d_out, int out_size) {
    const float* x          = (const float*)d_in[0];
    const float* grid       = (const float*)d_in[1];
    const float* coef       = (const float*)d_in[2];
    const float* scale_sp   = (const float*)d_in[3];
    const float* scale_base = (const float*)d_in[4];
    const float* bias_w     = (const float*)d_in[5];
    float* out = (float*)d_out;

    cudaFuncSetAttribute(gemm_kernel, cudaFuncAttributeMaxDynamicSharedMemorySize,
                         SMEM_BYTES);

    prep_kernel<<<896, 256>>>(x, grid, coef, scale_sp, scale_base, bias_w, out);

    dim3 gdim(BATCH / TILE_M, OUT_DIM / TILE_N, ZSPLIT);   // (16, 4, 4) = 256 CTAs
    gemm_kernel<<<gdim, 128, SMEM_BYTES>>>(out);
}